// round 4
// baseline (speedup 1.0000x reference)
#include <cuda_runtime.h>
#include <cstdint>

#define NUM_CLASSES 100000
#define BATCH 512
#define EMBED 512

#define S_SCALE 64.0f
#define COS_M 0.8775825618903728f
#define SIN_M 0.479425538604203f
#define TH_V (-0.8775825618903728f)
#define MM_V 0.23971276930210156f

// scratch (no allocations allowed)
__device__ float g_rnorm[NUM_CLASSES];
__device__ float g_rownll[BATCH];
__device__ int   g_label[BATCH];

// ---------------------------------------------------------------------------
// K0: label dtype autodetect + materialize int32 labels.
// View the label buffer as int32 words. First 512 words are in-bounds for
// both int32[512] and int64[512]. If the data is int64 (little-endian,
// values < 2^31), every odd word is zero. If int32, odd words are labels
// (all-zero probability ~0). One block, 512 threads.
// ---------------------------------------------------------------------------
__global__ void label_kernel(const int* __restrict__ raw) {
    __shared__ int s_or[16];
    int tid = threadIdx.x;
    int v = (tid & 1) ? raw[tid] : 0;      // OR of odd words among first 512
#pragma unroll
    for (int o = 16; o; o >>= 1) v |= __shfl_xor_sync(0xffffffffu, v, o);
    if ((tid & 31) == 0) s_or[tid >> 5] = v;
    __syncthreads();
    if (tid < 16) {
        int w = s_or[tid];
#pragma unroll
        for (int o = 8; o; o >>= 1) w |= __shfl_xor_sync(0xffffu, w, o);
        if (tid == 0) s_or[0] = w;
    }
    __syncthreads();
    bool is64 = (s_or[0] == 0);
    g_label[tid] = is64 ? raw[2 * tid] : raw[tid];
}

// ---------------------------------------------------------------------------
// K1: per-class inverse L2 norm of weight rows. One warp per row.
// ---------------------------------------------------------------------------
__global__ void rnorm_kernel(const float* __restrict__ w) {
    int gwarp = (blockIdx.x * blockDim.x + threadIdx.x) >> 5;
    int lane  = threadIdx.x & 31;
    if (gwarp >= NUM_CLASSES) return;
    const float4* row = (const float4*)(w + (size_t)gwarp * EMBED);
    float s = 0.f;
#pragma unroll
    for (int i = 0; i < EMBED / 4 / 32; i++) {  // 4 iterations
        float4 v = row[lane + i * 32];
        s += v.x * v.x + v.y * v.y + v.z * v.z + v.w * v.w;
    }
#pragma unroll
    for (int o = 16; o; o >>= 1) s += __shfl_xor_sync(0xffffffffu, s, o);
    if (lane == 0) g_rnorm[gwarp] = 1.0f / fmaxf(sqrtf(s), 1e-12f);
}

// ---------------------------------------------------------------------------
// K2: fused GEMM (3xTF32 error-compensated mma.sync) + ArcFace epilogue.
//   logits[m, n] = arcface( (X[m,:] . W[n,:]) * rnorm[n] ) * S
// Tiles: BM=128, BN=128, BK=16. 256 threads, 8 warps 2x4, warp tile 64x32.
// cp.async double-buffered smem.
// ---------------------------------------------------------------------------
#define BM 128
#define BN 128
#define BK 16
#define SSTRIDE 20   // BK + 4 floats pad
#define NKT (EMBED / BK)  // 32

__device__ __forceinline__ void cp_async16(void* smem, const void* gsrc, bool pred) {
    uint32_t sa = (uint32_t)__cvta_generic_to_shared(smem);
    int sz = pred ? 16 : 0;
    asm volatile("cp.async.cg.shared.global [%0], [%1], 16, %2;\n"
                 :: "r"(sa), "l"(gsrc), "r"(sz));
}

__device__ __forceinline__ uint32_t f32_to_tf32(float x) {
    uint32_t r;
    asm volatile("cvt.rna.tf32.f32 %0, %1;" : "=r"(r) : "f"(x));
    return r;
}

__device__ __forceinline__ void split_tf32(float x, uint32_t& hi, uint32_t& lo) {
    hi = f32_to_tf32(x);
    float r = x - __uint_as_float(hi);
    lo = f32_to_tf32(r);
}

__device__ __forceinline__ void mma_tf32(float* d, const uint32_t* a, const uint32_t* b) {
    asm volatile(
        "mma.sync.aligned.m16n8k8.row.col.f32.tf32.tf32.f32 "
        "{%0,%1,%2,%3}, {%4,%5,%6,%7}, {%8,%9}, {%0,%1,%2,%3};\n"
        : "+f"(d[0]), "+f"(d[1]), "+f"(d[2]), "+f"(d[3])
        : "r"(a[0]), "r"(a[1]), "r"(a[2]), "r"(a[3]), "r"(b[0]), "r"(b[1]));
}

__device__ __forceinline__ float arcface_val(float dot, float rn, bool is_label) {
    float c = dot * rn;
    if (is_label) {
        float s2 = fminf(fmaxf(1.0f - c * c, 0.0f), 1.0f);
        float sn = sqrtf(s2);
        float phi = c * COS_M - sn * SIN_M;
        c = (c > TH_V) ? phi : (c - MM_V);
    }
    return c * S_SCALE;
}

__global__ void __launch_bounds__(256, 2)
arcface_gemm_kernel(const float* __restrict__ X, const float* __restrict__ W,
                    float* __restrict__ out) {
    const int m0 = blockIdx.x * BM;
    const int n0 = blockIdx.y * BN;
    const int tid  = threadIdx.x;
    const int warp = tid >> 5, lane = tid & 31;
    const int wm = warp >> 2, wn = warp & 3;    // 2 x 4 warp grid
    const int grp = lane >> 2, tig = lane & 3;  // mma group / thread-in-group

    __shared__ float As[2][BM * SSTRIDE];
    __shared__ float Bs[2][BM * SSTRIDE];

    float acc[4][4][4];
#pragma unroll
    for (int i = 0; i < 4; i++)
#pragma unroll
        for (int j = 0; j < 4; j++)
#pragma unroll
            for (int k = 0; k < 4; k++) acc[i][j][k] = 0.f;

    auto load_tiles = [&](int kt, int buf) {
#pragma unroll
        for (int i = 0; i < 2; i++) {
            int idx = tid + i * 256;
            int row = idx >> 2;
            int c4  = (idx & 3) * 4;
            cp_async16(&As[buf][row * SSTRIDE + c4],
                       X + (size_t)(m0 + row) * EMBED + kt * BK + c4, true);
            bool p = (n0 + row) < NUM_CLASSES;
            cp_async16(&Bs[buf][row * SSTRIDE + c4],
                       W + (size_t)(n0 + row) * EMBED + kt * BK + c4, p);
        }
        asm volatile("cp.async.commit_group;\n");
    };

    load_tiles(0, 0);

    for (int kt = 0; kt < NKT; kt++) {
        if (kt + 1 < NKT) {
            load_tiles(kt + 1, (kt + 1) & 1);
            asm volatile("cp.async.wait_group 1;\n");
        } else {
            asm volatile("cp.async.wait_group 0;\n");
        }
        __syncthreads();

        const float* Ab = As[kt & 1];
        const float* Bb = Bs[kt & 1];
#pragma unroll
        for (int kk = 0; kk < BK / 8; kk++) {
            int k0 = kk * 8;
            uint32_t ahi[4][4], alo[4][4];
#pragma unroll
            for (int mt = 0; mt < 4; mt++) {
                int r = wm * 64 + mt * 16 + grp;
                split_tf32(Ab[r * SSTRIDE + k0 + tig],           ahi[mt][0], alo[mt][0]);
                split_tf32(Ab[(r + 8) * SSTRIDE + k0 + tig],     ahi[mt][1], alo[mt][1]);
                split_tf32(Ab[r * SSTRIDE + k0 + tig + 4],       ahi[mt][2], alo[mt][2]);
                split_tf32(Ab[(r + 8) * SSTRIDE + k0 + tig + 4], ahi[mt][3], alo[mt][3]);
            }
#pragma unroll
            for (int nt = 0; nt < 4; nt++) {
                int c = wn * 32 + nt * 8 + grp;
                uint32_t bhi[2], blo[2];
                split_tf32(Bb[c * SSTRIDE + k0 + tig],     bhi[0], blo[0]);
                split_tf32(Bb[c * SSTRIDE + k0 + tig + 4], bhi[1], blo[1]);
#pragma unroll
                for (int mt = 0; mt < 4; mt++) {
                    mma_tf32(acc[mt][nt], alo[mt], bhi);   // small terms first
                    mma_tf32(acc[mt][nt], ahi[mt], blo);
                    mma_tf32(acc[mt][nt], ahi[mt], bhi);
                }
            }
        }
        __syncthreads();
    }

    // Epilogue: scale by rnorm[n], ArcFace margin at the (detected) label column.
#pragma unroll
    for (int mt = 0; mt < 4; mt++) {
        int m_lo = m0 + wm * 64 + mt * 16 + grp;
        int m_hi = m_lo + 8;
        int lbl_lo = g_label[m_lo];
        int lbl_hi = g_label[m_hi];
#pragma unroll
        for (int nt = 0; nt < 4; nt++) {
            int n = n0 + wn * 32 + nt * 8 + 2 * tig;
            bool v0 = n < NUM_CLASSES;
            bool v1 = (n + 1) < NUM_CLASSES;
            float rn0 = v0 ? g_rnorm[n] : 0.f;
            float rn1 = v1 ? g_rnorm[n + 1] : 0.f;
            float* a = acc[mt][nt];
            if (v0) {
                out[(size_t)m_lo * NUM_CLASSES + n] = arcface_val(a[0], rn0, n == lbl_lo);
                out[(size_t)m_hi * NUM_CLASSES + n] = arcface_val(a[2], rn0, n == lbl_hi);
            }
            if (v1) {
                out[(size_t)m_lo * NUM_CLASSES + n + 1] = arcface_val(a[1], rn1, (n + 1) == lbl_lo);
                out[(size_t)m_hi * NUM_CLASSES + n + 1] = arcface_val(a[3], rn1, (n + 1) == lbl_hi);
            }
        }
    }
}

// ---------------------------------------------------------------------------
// K3: per-row online logsumexp over 100000 logits -> per-row NLL.
// ---------------------------------------------------------------------------
__global__ void lse_kernel(const float* __restrict__ logits) {
    const int row = blockIdx.x;
    const int tid = threadIdx.x;
    const float4* p = (const float4*)(logits + (size_t)row * NUM_CLASSES);
    const int n4 = NUM_CLASSES / 4;  // 25000

    float m = -INFINITY, s = 0.f;
    for (int i = tid; i < n4; i += 512) {
        float4 v = p[i];
        float mx = fmaxf(fmaxf(v.x, v.y), fmaxf(v.z, v.w));
        if (mx > m) { s *= __expf(m - mx); m = mx; }
        s += __expf(v.x - m) + __expf(v.y - m) + __expf(v.z - m) + __expf(v.w - m);
    }

    __shared__ float sm[512];
    __shared__ float ss[512];
    sm[tid] = m; ss[tid] = s;
    __syncthreads();
    for (int o = 256; o; o >>= 1) {
        if (tid < o) {
            float m1 = sm[tid], s1 = ss[tid];
            float m2 = sm[tid + o], s2 = ss[tid + o];
            float mm = fmaxf(m1, m2);
            sm[tid] = mm;
            ss[tid] = s1 * __expf(m1 - mm) + s2 * __expf(m2 - mm);
        }
        __syncthreads();
    }
    if (tid == 0) {
        float logZ = sm[0] + __logf(ss[0]);
        int lbl = g_label[row];
        g_rownll[row] = logZ - logits[(size_t)row * NUM_CLASSES + lbl];
    }
}

// ---------------------------------------------------------------------------
// K4: loss = mean(rownll). Single block, deterministic tree reduce.
// ---------------------------------------------------------------------------
__global__ void loss_kernel(float* __restrict__ out, int out_size) {
    __shared__ float sm[BATCH];
    sm[threadIdx.x] = g_rownll[threadIdx.x];
    __syncthreads();
    for (int o = 256; o; o >>= 1) {
        if (threadIdx.x < o) sm[threadIdx.x] += sm[threadIdx.x + o];
        __syncthreads();
    }
    if (threadIdx.x == 0) {
        long long total = (long long)BATCH * NUM_CLASSES;
        if ((long long)out_size > total)
            out[total] = sm[0] * (1.0f / BATCH);
    }
}

// ---------------------------------------------------------------------------
extern "C" void kernel_launch(void* const* d_in, const int* in_sizes, int n_in,
                              void* d_out, int out_size) {
    const float* X       = (const float*)d_in[0];   // [512, 512]
    const int*   labelRaw = (const int*)d_in[1];    // [512] int32 or int64 (autodetected)
    const float* W       = (const float*)d_in[2];   // [100000, 512]
    float* out = (float*)d_out;

    // K0: label dtype detect + materialize
    label_kernel<<<1, BATCH>>>(labelRaw);

    // K1: inverse norms
    rnorm_kernel<<<NUM_CLASSES / 8, 256>>>(W);

    // K2: fused GEMM + ArcFace epilogue
    dim3 grid(BATCH / BM, (NUM_CLASSES + BN - 1) / BN);  // (4, 782)
    arcface_gemm_kernel<<<grid, 256>>>(X, W, out);

    // K3: per-row logsumexp -> NLL
    lse_kernel<<<BATCH, 512>>>(out);

    // K4: mean loss
    loss_kernel<<<1, BATCH>>>(out, out_size);
}

// round 5
// speedup vs baseline: 2.2509x; 2.2509x over previous
#include <cuda_runtime.h>
#include <cstdint>

#define NUM_CLASSES 100000
#define BATCH 512
#define EMBED 512

#define S_SCALE 64.0f
#define COS_M 0.8775825618903728f
#define SIN_M 0.479425538604203f
#define TH_V (-0.8775825618903728f)
#define MM_V 0.23971276930210156f

// scratch (no allocations allowed)
__device__ float g_rnorm[NUM_CLASSES];
__device__ float g_rownll[BATCH];
__device__ int   g_label[BATCH];

// ---------------------------------------------------------------------------
// K0: label dtype autodetect + materialize int32 labels.
// If the buffer is int64 (LE, values < 2^31), all odd int32 words are zero.
// ---------------------------------------------------------------------------
__global__ void label_kernel(const int* __restrict__ raw) {
    __shared__ int s_or[16];
    int tid = threadIdx.x;
    int v = (tid & 1) ? raw[tid] : 0;
#pragma unroll
    for (int o = 16; o; o >>= 1) v |= __shfl_xor_sync(0xffffffffu, v, o);
    if ((tid & 31) == 0) s_or[tid >> 5] = v;
    __syncthreads();
    if (tid < 16) {
        int w = s_or[tid];
#pragma unroll
        for (int o = 8; o; o >>= 1) w |= __shfl_xor_sync(0xffffu, w, o);
        if (tid == 0) s_or[0] = w;
    }
    __syncthreads();
    bool is64 = (s_or[0] == 0);
    g_label[tid] = is64 ? raw[2 * tid] : raw[tid];
}

// ---------------------------------------------------------------------------
// K1: per-class inverse L2 norm of weight rows. One warp per row.
// ---------------------------------------------------------------------------
__global__ void rnorm_kernel(const float* __restrict__ w) {
    int gwarp = (blockIdx.x * blockDim.x + threadIdx.x) >> 5;
    int lane  = threadIdx.x & 31;
    if (gwarp >= NUM_CLASSES) return;
    const float4* row = (const float4*)(w + (size_t)gwarp * EMBED);
    float s = 0.f;
#pragma unroll
    for (int i = 0; i < EMBED / 4 / 32; i++) {  // 4 iterations
        float4 v = row[lane + i * 32];
        s += v.x * v.x + v.y * v.y + v.z * v.z + v.w * v.w;
    }
#pragma unroll
    for (int o = 16; o; o >>= 1) s += __shfl_xor_sync(0xffffffffu, s, o);
    if (lane == 0) g_rnorm[gwarp] = 1.0f / fmaxf(sqrtf(s), 1e-12f);
}

// ---------------------------------------------------------------------------
// K2: fused GEMM (single-pass TF32 mma.sync m16n8k8) + ArcFace epilogue.
// TF32 GEMM error ~2.8e-4 normwise (measured via quadrature in R1/R2,
// threshold 1e-3) — 3x fewer MMAs than the compensated variant.
// Tiles: BM=128, BN=128, BK=16. 256 threads, 8 warps 2x4, warp tile 64x32.
// ---------------------------------------------------------------------------
#define BM 128
#define BN 128
#define BK 16
#define SSTRIDE 20   // BK + 4 floats pad
#define NKT (EMBED / BK)  // 32

__device__ __forceinline__ void cp_async16(void* smem, const void* gsrc, bool pred) {
    uint32_t sa = (uint32_t)__cvta_generic_to_shared(smem);
    int sz = pred ? 16 : 0;
    asm volatile("cp.async.cg.shared.global [%0], [%1], 16, %2;\n"
                 :: "r"(sa), "l"(gsrc), "r"(sz));
}

__device__ __forceinline__ uint32_t f32_to_tf32(float x) {
    uint32_t r;
    asm volatile("cvt.rna.tf32.f32 %0, %1;" : "=r"(r) : "f"(x));
    return r;
}

__device__ __forceinline__ void mma_tf32(float* d, const uint32_t* a, const uint32_t* b) {
    asm volatile(
        "mma.sync.aligned.m16n8k8.row.col.f32.tf32.tf32.f32 "
        "{%0,%1,%2,%3}, {%4,%5,%6,%7}, {%8,%9}, {%0,%1,%2,%3};\n"
        : "+f"(d[0]), "+f"(d[1]), "+f"(d[2]), "+f"(d[3])
        : "r"(a[0]), "r"(a[1]), "r"(a[2]), "r"(a[3]), "r"(b[0]), "r"(b[1]));
}

__device__ __forceinline__ float arcface_val(float dot, float rn, bool is_label) {
    float c = dot * rn;
    if (is_label) {
        float s2 = fminf(fmaxf(1.0f - c * c, 0.0f), 1.0f);
        float sn = sqrtf(s2);
        float phi = c * COS_M - sn * SIN_M;
        c = (c > TH_V) ? phi : (c - MM_V);
    }
    return c * S_SCALE;
}

__global__ void __launch_bounds__(256, 2)
arcface_gemm_kernel(const float* __restrict__ X, const float* __restrict__ W,
                    float* __restrict__ out) {
    const int m0 = blockIdx.x * BM;
    const int n0 = blockIdx.y * BN;
    const int tid  = threadIdx.x;
    const int warp = tid >> 5, lane = tid & 31;
    const int wm = warp >> 2, wn = warp & 3;    // 2 x 4 warp grid
    const int grp = lane >> 2, tig = lane & 3;  // mma group / thread-in-group

    __shared__ float As[2][BM * SSTRIDE];
    __shared__ float Bs[2][BM * SSTRIDE];

    float acc[4][4][4];
#pragma unroll
    for (int i = 0; i < 4; i++)
#pragma unroll
        for (int j = 0; j < 4; j++)
#pragma unroll
            for (int k = 0; k < 4; k++) acc[i][j][k] = 0.f;

    auto load_tiles = [&](int kt, int buf) {
#pragma unroll
        for (int i = 0; i < 2; i++) {
            int idx = tid + i * 256;
            int row = idx >> 2;
            int c4  = (idx & 3) * 4;
            cp_async16(&As[buf][row * SSTRIDE + c4],
                       X + (size_t)(m0 + row) * EMBED + kt * BK + c4, true);
            bool p = (n0 + row) < NUM_CLASSES;
            cp_async16(&Bs[buf][row * SSTRIDE + c4],
                       W + (size_t)(n0 + row) * EMBED + kt * BK + c4, p);
        }
        asm volatile("cp.async.commit_group;\n");
    };

    load_tiles(0, 0);

    for (int kt = 0; kt < NKT; kt++) {
        if (kt + 1 < NKT) {
            load_tiles(kt + 1, (kt + 1) & 1);
            asm volatile("cp.async.wait_group 1;\n");
        } else {
            asm volatile("cp.async.wait_group 0;\n");
        }
        __syncthreads();

        const float* Ab = As[kt & 1];
        const float* Bb = Bs[kt & 1];
#pragma unroll
        for (int kk = 0; kk < BK / 8; kk++) {
            int k0 = kk * 8;
            uint32_t af[4][4], bf[4][2];
#pragma unroll
            for (int mt = 0; mt < 4; mt++) {
                int r = wm * 64 + mt * 16 + grp;
                af[mt][0] = f32_to_tf32(Ab[r * SSTRIDE + k0 + tig]);
                af[mt][1] = f32_to_tf32(Ab[(r + 8) * SSTRIDE + k0 + tig]);
                af[mt][2] = f32_to_tf32(Ab[r * SSTRIDE + k0 + tig + 4]);
                af[mt][3] = f32_to_tf32(Ab[(r + 8) * SSTRIDE + k0 + tig + 4]);
            }
#pragma unroll
            for (int nt = 0; nt < 4; nt++) {
                int c = wn * 32 + nt * 8 + grp;
                bf[nt][0] = f32_to_tf32(Bb[c * SSTRIDE + k0 + tig]);
                bf[nt][1] = f32_to_tf32(Bb[c * SSTRIDE + k0 + tig + 4]);
            }
#pragma unroll
            for (int mt = 0; mt < 4; mt++)
#pragma unroll
                for (int nt = 0; nt < 4; nt++)
                    mma_tf32(acc[mt][nt], af[mt], bf[nt]);
        }
        __syncthreads();
    }

    // Epilogue: scale by rnorm[n], ArcFace margin at the label column, * S.
#pragma unroll
    for (int mt = 0; mt < 4; mt++) {
        int m_lo = m0 + wm * 64 + mt * 16 + grp;
        int m_hi = m_lo + 8;
        int lbl_lo = g_label[m_lo];
        int lbl_hi = g_label[m_hi];
#pragma unroll
        for (int nt = 0; nt < 4; nt++) {
            int n = n0 + wn * 32 + nt * 8 + 2 * tig;
            bool v0 = n < NUM_CLASSES;
            bool v1 = (n + 1) < NUM_CLASSES;
            float rn0 = v0 ? g_rnorm[n] : 0.f;
            float rn1 = v1 ? g_rnorm[n + 1] : 0.f;
            float* a = acc[mt][nt];
            if (v0) {
                out[(size_t)m_lo * NUM_CLASSES + n] = arcface_val(a[0], rn0, n == lbl_lo);
                out[(size_t)m_hi * NUM_CLASSES + n] = arcface_val(a[2], rn0, n == lbl_hi);
            }
            if (v1) {
                out[(size_t)m_lo * NUM_CLASSES + n + 1] = arcface_val(a[1], rn1, (n + 1) == lbl_lo);
                out[(size_t)m_hi * NUM_CLASSES + n + 1] = arcface_val(a[3], rn1, (n + 1) == lbl_hi);
            }
        }
    }
}

// ---------------------------------------------------------------------------
// K3: per-row online logsumexp over 100000 logits -> per-row NLL.
// ---------------------------------------------------------------------------
__global__ void lse_kernel(const float* __restrict__ logits) {
    const int row = blockIdx.x;
    const int tid = threadIdx.x;
    const float4* p = (const float4*)(logits + (size_t)row * NUM_CLASSES);
    const int n4 = NUM_CLASSES / 4;  // 25000

    float m = -INFINITY, s = 0.f;
    for (int i = tid; i < n4; i += 512) {
        float4 v = p[i];
        float mx = fmaxf(fmaxf(v.x, v.y), fmaxf(v.z, v.w));
        if (mx > m) { s *= __expf(m - mx); m = mx; }
        s += __expf(v.x - m) + __expf(v.y - m) + __expf(v.z - m) + __expf(v.w - m);
    }

    __shared__ float sm[512];
    __shared__ float ss[512];
    sm[tid] = m; ss[tid] = s;
    __syncthreads();
    for (int o = 256; o; o >>= 1) {
        if (tid < o) {
            float m1 = sm[tid], s1 = ss[tid];
            float m2 = sm[tid + o], s2 = ss[tid + o];
            float mm = fmaxf(m1, m2);
            sm[tid] = mm;
            ss[tid] = s1 * __expf(m1 - mm) + s2 * __expf(m2 - mm);
        }
        __syncthreads();
    }
    if (tid == 0) {
        float logZ = sm[0] + __logf(ss[0]);
        int lbl = g_label[row];
        g_rownll[row] = logZ - logits[(size_t)row * NUM_CLASSES + lbl];
    }
}

// ---------------------------------------------------------------------------
// K4: loss = mean(rownll). Single block, deterministic tree reduce.
// ---------------------------------------------------------------------------
__global__ void loss_kernel(float* __restrict__ out, int out_size) {
    __shared__ float sm[BATCH];
    sm[threadIdx.x] = g_rownll[threadIdx.x];
    __syncthreads();
    for (int o = 256; o; o >>= 1) {
        if (threadIdx.x < o) sm[threadIdx.x] += sm[threadIdx.x + o];
        __syncthreads();
    }
    if (threadIdx.x == 0) {
        long long total = (long long)BATCH * NUM_CLASSES;
        if ((long long)out_size > total)
            out[total] = sm[0] * (1.0f / BATCH);
    }
}

// ---------------------------------------------------------------------------
extern "C" void kernel_launch(void* const* d_in, const int* in_sizes, int n_in,
                              void* d_out, int out_size) {
    const float* X        = (const float*)d_in[0];   // [512, 512]
    const int*   labelRaw = (const int*)d_in[1];     // int32 or int64 (autodetected)
    const float* W        = (const float*)d_in[2];   // [100000, 512]
    float* out = (float*)d_out;

    // K0: label dtype detect + materialize
    label_kernel<<<1, BATCH>>>(labelRaw);

    // K1: inverse norms
    rnorm_kernel<<<NUM_CLASSES / 8, 256>>>(W);

    // K2: fused TF32 GEMM + ArcFace epilogue
    dim3 grid(BATCH / BM, (NUM_CLASSES + BN - 1) / BN);  // (4, 782)
    arcface_gemm_kernel<<<grid, 256>>>(X, W, out);

    // K3: per-row logsumexp -> NLL
    lse_kernel<<<BATCH, 512>>>(out);

    // K4: mean loss
    loss_kernel<<<1, BATCH>>>(out, out_size);
}